// round 2
// baseline (speedup 1.0000x reference)
#include <cuda_runtime.h>

// InnerProduct: ip[r,p] = sum_f w[p,f]^2 * sum_e x[r,f,e]^2
// x: [32768, 64, 128] f32, w: [10, 64] f32, out: [32768, 10] f32
//
// DRAM-bound (1 GiB read). Persistent grid-stride CTAs: each CTA loops over
// ~30 rows, one 32KB fully-coalesced read per row. Double-buffered xsq smem
// -> exactly one __syncthreads per row; next row's 8 LDG.128 per thread issue
// while the previous row's tail computes.

#define BATCH    32768
#define N_FIELDS 64
#define EMBED    128
#define OUT_SZ   10
#define THREADS  256
#define GRID     1184   // ~8 CTAs/SM worth of persistent blocks

__global__ __launch_bounds__(THREADS)
void innerproduct_kernel(const float* __restrict__ x,
                         const float* __restrict__ w,
                         float* __restrict__ out)
{
    const int tid  = threadIdx.x;
    const int warp = tid >> 5;
    const int lane = tid & 31;

    __shared__ float xsq[2][N_FIELDS];

    // Tail-thread setup: tid < 160 -> output p = tid/16, sub-lane g = tid%16,
    // owns fields g*4..g*4+3. Hoist squared weights into registers once.
    const int p = tid >> 4;
    const int g = tid & 15;
    float wsq[4] = {0.f, 0.f, 0.f, 0.f};
    if (tid < OUT_SZ * 16) {
#pragma unroll
        for (int k = 0; k < 4; k++) {
            float wv = __ldg(&w[p * N_FIELDS + g * 4 + k]);
            wsq[k] = wv * wv;
        }
    }

    int buf = 0;
    for (int row = blockIdx.x; row < BATCH; row += GRID, buf ^= 1) {
        const float4* __restrict__ xr =
            reinterpret_cast<const float4*>(x) + (size_t)row * (N_FIELDS * EMBED / 4);

        // Warp w owns fields 8w..8w+7 (contiguous 4KB per warp).
        // Lane l loads float4 #l of each field: 8 independent LDG.128.
        float acc[8];
#pragma unroll
        for (int i = 0; i < 8; i++) {
            float4 v = xr[(warp * 8 + i) * (EMBED / 4) + lane];
            acc[i] = v.x * v.x + v.y * v.y + v.z * v.z + v.w * v.w;
        }

#pragma unroll
        for (int i = 0; i < 8; i++) {
#pragma unroll
            for (int s = 16; s >= 1; s >>= 1)
                acc[i] += __shfl_xor_sync(0xffffffffu, acc[i], s);
        }
        if (lane == 0) {
#pragma unroll
            for (int i = 0; i < 8; i++)
                xsq[buf][warp * 8 + i] = acc[i];
        }
        __syncthreads();

        // Tail: 10 outputs x 16 threads (warps 0..4). Double-buffered xsq
        // means no trailing barrier: next row writes the other buffer.
        if (tid < OUT_SZ * 16) {
            float s = 0.f;
#pragma unroll
            for (int k = 0; k < 4; k++)
                s = fmaf(xsq[buf][g * 4 + k], wsq[k], s);
#pragma unroll
            for (int sh = 8; sh >= 1; sh >>= 1)
                s += __shfl_xor_sync(0xffffffffu, s, sh);
            if (g == 0)
                out[row * OUT_SZ + p] = s;
        }
    }
}

extern "C" void kernel_launch(void* const* d_in, const int* in_sizes, int n_in,
                              void* d_out, int out_size)
{
    const float* x = (const float*)d_in[0];
    const float* w = (const float*)d_in[1];
    float* out = (float*)d_out;

    innerproduct_kernel<<<GRID, THREADS>>>(x, w, out);
}

// round 3
// speedup vs baseline: 1.2117x; 1.2117x over previous
#include <cuda_runtime.h>

// InnerProduct: ip[r,p] = sum_f w[p,f]^2 * sum_e x[r,f,e]^2
// x: [32768, 64, 128] f32, w: [10, 64] f32, out: [32768, 10] f32
//
// DRAM-bound (1 GiB read of x). One-shot CTA per row (R1 structure: massive
// oversubscription keeps the load pipe full). Per-warp 8-field partials are
// reduced with a fold-and-split multi-value reduction: 9 SHFLs instead of 40,
// shortening each CTA's post-load tail and raising CTA turnover.

#define BATCH    32768
#define N_FIELDS 64
#define EMBED    128
#define OUT_SZ   10
#define THREADS  256

__global__ __launch_bounds__(THREADS)
void innerproduct_kernel(const float* __restrict__ x,
                         const float* __restrict__ w,
                         float* __restrict__ out)
{
    const int r    = blockIdx.x;
    const int tid  = threadIdx.x;
    const int warp = tid >> 5;
    const int lane = tid & 31;

    __shared__ float xsq[N_FIELDS];

    const float4* __restrict__ xr =
        reinterpret_cast<const float4*>(x) + (size_t)r * (N_FIELDS * EMBED / 4);

    // Front-batched loads: warp owns fields 8w..8w+7 (contiguous 4KB),
    // lane l takes float4 #l of each field. 8 independent LDG.128.
    float4 vv[8];
#pragma unroll
    for (int i = 0; i < 8; i++)
        vv[i] = xr[(warp * 8 + i) * (EMBED / 4) + lane];

    // Weight loads issue now too — latency hides under the x-load wait.
    const int p = tid >> 4;   // output 0..9 for tid < 160
    const int g = tid & 15;   // sub-lane; owns fields g*4..g*4+3
    float wsq[4] = {0.f, 0.f, 0.f, 0.f};
    if (tid < OUT_SZ * 16) {
#pragma unroll
        for (int k = 0; k < 4; k++) {
            float wv = __ldg(&w[p * N_FIELDS + g * 4 + k]);
            wsq[k] = wv * wv;
        }
    }

    float v[8];
#pragma unroll
    for (int i = 0; i < 8; i++)
        v[i] = vv[i].x * vv[i].x + vv[i].y * vv[i].y
             + vv[i].z * vv[i].z + vv[i].w * vv[i].w;

    // Fold-and-split multi-value warp reduce: 8 fields -> 1 per lane in
    // 9 SHFLs. After the folds, lane l holds field f = (l>>2)&7 fully
    // reduced across all 32 lanes.
    {
        const bool hi16 = (lane & 16) != 0;
#pragma unroll
        for (int j = 0; j < 4; j++) {
            float send = hi16 ? v[j] : v[j + 4];
            float recv = __shfl_xor_sync(0xffffffffu, send, 16);
            v[j] = (hi16 ? v[j + 4] : v[j]) + recv;
        }
        const bool hi8 = (lane & 8) != 0;
#pragma unroll
        for (int j = 0; j < 2; j++) {
            float send = hi8 ? v[j] : v[j + 2];
            float recv = __shfl_xor_sync(0xffffffffu, send, 8);
            v[j] = (hi8 ? v[j + 2] : v[j]) + recv;
        }
        const bool hi4 = (lane & 4) != 0;
        {
            float send = hi4 ? v[0] : v[1];
            float recv = __shfl_xor_sync(0xffffffffu, send, 4);
            v[0] = (hi4 ? v[1] : v[0]) + recv;
        }
        v[0] += __shfl_xor_sync(0xffffffffu, v[0], 2);
        v[0] += __shfl_xor_sync(0xffffffffu, v[0], 1);
    }
    if ((lane & 3) == 0)
        xsq[warp * 8 + ((lane >> 2) & 7)] = v[0];
    __syncthreads();

    // Tail: 10 outputs x 16 threads (warps 0..4).
    if (tid < OUT_SZ * 16) {
        float s = 0.f;
#pragma unroll
        for (int k = 0; k < 4; k++)
            s = fmaf(xsq[g * 4 + k], wsq[k], s);
#pragma unroll
        for (int sh = 8; sh >= 1; sh >>= 1)
            s += __shfl_xor_sync(0xffffffffu, s, sh);
        if (g == 0)
            out[r * OUT_SZ + p] = s;
    }
}

extern "C" void kernel_launch(void* const* d_in, const int* in_sizes, int n_in,
                              void* d_out, int out_size)
{
    const float* x = (const float*)d_in[0];
    const float* w = (const float*)d_in[1];
    float* out = (float*)d_out;

    innerproduct_kernel<<<BATCH, THREADS>>>(x, w, out);
}